// round 7
// baseline (speedup 1.0000x reference)
#include <cuda_runtime.h>

// Problem constants (fixed by setup_inputs: N=4, M=8192, D=64, k=16)
#define NB 4
#define MP 8192
#define DD 64
#define KNN 16
#define TM 64           // rows per CTA
#define TN 64           // candidate cols per tile
#define NTHREADS 256    // 16x16 threads, 4x4 micro-tile each
#define NEDGES (NB * MP * KNN)   // 524288

// Static shared memory (< 48KB => launch cannot fail on smem):
//   At[64][64] k-major (16 KB), U = union(Bt[64][64] k-major, Dt[64][65]) (16.6 KB),
//   x2r[64], x2c[64].  Total ~33.2 KB.
#define DT_PITCH 65

__global__ __launch_bounds__(NTHREADS)
void knn_topk_kernel(const float* __restrict__ x,
                     float* __restrict__ out,      // float32 output dtype!
                     int write_dst) {
    __shared__ float At[DD * TM];          // At[d][m]
    __shared__ float U[TM * DT_PITCH];     // Bt[d][n] (pitch 64) then Dt[r][c] (pitch 65)
    __shared__ float x2r[TM];
    __shared__ float x2c[TN];

    const int tid   = threadIdx.x;
    const int batch = blockIdx.x >> 7;          // 128 row-tiles per batch
    const int rtile = blockIdx.x & 127;
    const float* xb = x + (size_t)batch * MP * DD;
    const int row0  = rtile * TM;

    // ---- Load A tile transposed to k-major: At[d][m] = xb[(row0+m)*DD + d] ----
    #pragma unroll
    for (int it = 0; it < 4; ++it) {
        int idx = it * NTHREADS + tid;          // 0..1023
        int m   = idx & 63;
        int d4  = idx >> 6;                     // 0..15
        float4 v = *reinterpret_cast<const float4*>(xb + (size_t)(row0 + m) * DD + d4 * 4);
        At[(d4 * 4 + 0) * TM + m] = v.x;
        At[(d4 * 4 + 1) * TM + m] = v.y;
        At[(d4 * 4 + 2) * TM + m] = v.z;
        At[(d4 * 4 + 3) * TM + m] = v.w;
    }
    __syncthreads();

    // Row squared norms (threads 0..63)
    if (tid < TM) {
        float s = 0.f;
        #pragma unroll
        for (int d = 0; d < DD; ++d) {
            float a = At[d * TM + tid];
            s = fmaf(a, a, s);
        }
        x2r[tid] = s;
    }

    const int ty = tid >> 4;        // 0..15
    const int tx = tid & 15;        // 0..15
    const int r0 = ty * 4;
    const int c0 = tx * 4;

    // Running top-16 (ascending d2), register-resident (static indexing only)
    float best[KNN];
    int   bidx[KNN];
    #pragma unroll
    for (int i = 0; i < KNN; ++i) { best[i] = __int_as_float(0x7f800000); bidx[i] = 0; }

    for (int ct = 0; ct < MP / TN; ++ct) {
        const int col0 = ct * TN;

        // ---- Load B tile transposed to k-major into U: Bt[d][n] ----
        #pragma unroll
        for (int it = 0; it < 4; ++it) {
            int idx = it * NTHREADS + tid;
            int n   = idx & 63;
            int d4  = idx >> 6;
            float4 v = *reinterpret_cast<const float4*>(xb + (size_t)(col0 + n) * DD + d4 * 4);
            U[(d4 * 4 + 0) * TN + n] = v.x;
            U[(d4 * 4 + 1) * TN + n] = v.y;
            U[(d4 * 4 + 2) * TN + n] = v.z;
            U[(d4 * 4 + 3) * TN + n] = v.w;
        }
        __syncthreads();   // Bt visible (also: x2r visible on first iteration)

        // Candidate squared norms for this tile
        if (tid < TN) {
            float s = 0.f;
            #pragma unroll
            for (int d = 0; d < DD; ++d) {
                float b = U[d * TN + tid];
                s = fmaf(b, b, s);
            }
            x2c[tid] = s;
        }

        // ---- 64x64x64 GEMM: 4x4 micro-tile per thread ----
        float acc[4][4];
        #pragma unroll
        for (int i = 0; i < 4; ++i)
            #pragma unroll
            for (int j = 0; j < 4; ++j) acc[i][j] = 0.f;

        #pragma unroll 8
        for (int kk = 0; kk < DD; ++kk) {
            float4 av = *reinterpret_cast<const float4*>(&At[kk * TM + r0]);
            float4 bv = *reinterpret_cast<const float4*>(&U[kk * TN + c0]);
            float a[4] = {av.x, av.y, av.z, av.w};
            float b[4] = {bv.x, bv.y, bv.z, bv.w};
            #pragma unroll
            for (int i = 0; i < 4; ++i)
                #pragma unroll
                for (int j = 0; j < 4; ++j)
                    acc[i][j] = fmaf(a[i], b[j], acc[i][j]);
        }
        __syncthreads();   // all GEMM reads of U(Bt) done; x2c written

        // ---- Epilogue: d2 = (x2r + x2c) - 2*dot, write Dt over the Bt space.
        // fmaf(-2, dot, t) rounds identically to the reference's t - 2*dot. ----
        #pragma unroll
        for (int i = 0; i < 4; ++i) {
            float xr = x2r[r0 + i];
            #pragma unroll
            for (int j = 0; j < 4; ++j) {
                float t = xr + x2c[c0 + j];
                U[(r0 + i) * DT_PITCH + (c0 + j)] = fmaf(-2.f, acc[i][j], t);
            }
        }
        __syncthreads();

        // ---- Per-row top-16 update: thread tid (<64) scans row tid ----
        if (tid < TM) {
            const float* drow = &U[tid * DT_PITCH];   // pitch 65 -> conflict-free
            #pragma unroll 4
            for (int c = 0; c < TN; ++c) {
                float v = drow[c];
                if (v < best[KNN - 1]) {          // strict < keeps stable tie order
                    best[KNN - 1] = v;
                    bidx[KNN - 1] = col0 + c;
                    #pragma unroll
                    for (int j = KNN - 1; j > 0; --j) {
                        if (best[j] < best[j - 1]) {
                            float tv = best[j]; best[j] = best[j - 1]; best[j - 1] = tv;
                            int   ti = bidx[j]; bidx[j] = bidx[j - 1]; bidx[j - 1] = ti;
                        }
                    }
                }
            }
        }
        __syncthreads();   // scanners done reading U before next Bt overwrites it
    }

    // ---- Writeback as FLOAT32 (the recorded __output__ dtype):
    //   output 0: src = (float)(neighbor id + batch offset), at out[0 : NEDGES)
    //   output 1: dst = (float)node id, at out[NEDGES : 2*NEDGES).
    //   Ids <= 32767 are exactly representable in f32. ----
    if (tid < TM) {
        int gid  = batch * MP + row0 + tid;
        int base = gid * KNN;
        int off  = batch * MP;
        #pragma unroll
        for (int t = 0; t < KNN; ++t) {
            out[base + t] = (float)(bidx[t] + off);
        }
        if (write_dst) {
            float fgid = (float)gid;
            #pragma unroll
            for (int t = 0; t < KNN; ++t) {
                out[NEDGES + base + t] = fgid;
            }
        }
    }
}

extern "C" void kernel_launch(void* const* d_in, const int* in_sizes, int n_in,
                              void* d_out, int out_size) {
    // Bind x = largest input (robust whether in_sizes is elements or bytes;
    // x is 2097152 floats / 8388608 bytes, k is a scalar).
    const float* x = (const float*)d_in[0];
    long long best_sz = -1;
    for (int i = 0; i < n_in; ++i) {
        if ((long long)in_sizes[i] > best_sz) {
            best_sz = in_sizes[i];
            x = (const float*)d_in[i];
        }
    }

    // Write dst only if the buffer provably holds both outputs
    // (1048576 elements, or the same expressed in bytes).
    const int write_dst = (out_size >= 2 * NEDGES);

    // Static smem only, 256 threads: this launch cannot fail.
    knn_topk_kernel<<<NB * (MP / TM), NTHREADS>>>(x, (float*)d_out, write_dst);
}

// round 8
// speedup vs baseline: 1.5436x; 1.5436x over previous
#include <cuda_runtime.h>

// Problem constants (fixed by setup_inputs: N=4, M=8192, D=64, k=16)
#define NB 4
#define MP 8192
#define DD 64
#define KNN 16
#define TM 128
#define TN 128
#define NTHREADS 256
#define NEDGES (NB * MP * KNN)   // 524288

#define PA 132   // At/Bt pitch in floats (d-major tiles)
#define PD 131   // Dt pitch in floats (odd -> conflict-free row scan)

// shared layout (floats)
#define SM_AT  0
#define SM_BT  (64 * PA)
#define SM_DT  (2 * 64 * PA)
#define SM_X2R (2 * 64 * PA + 128 * PD)
#define SM_X2C (SM_X2R + 128)
#define SMEM_FLOATS (SM_X2C + 128)
#define SMEM_BYTES  (SMEM_FLOATS * 4)   // 135,680 B

typedef unsigned long long ull;

__device__ __forceinline__ ull ffma2(ull a, ull b, ull c) {
    ull d;
    asm("fma.rn.f32x2 %0, %1, %2, %3;" : "=l"(d) : "l"(a), "l"(b), "l"(c));
    return d;
}
__device__ __forceinline__ ull splat2(float v) {
    ull d;
    unsigned u = __float_as_uint(v);
    asm("mov.b64 %0, {%1, %1};" : "=l"(d) : "r"(u));
    return d;
}
__device__ __forceinline__ float lane_lo(ull v) { return __uint_as_float((unsigned)v); }
__device__ __forceinline__ float lane_hi(ull v) { return __uint_as_float((unsigned)(v >> 32)); }

__global__ __launch_bounds__(NTHREADS, 1)
void knn_topk_kernel(const float* __restrict__ x,
                     float* __restrict__ out,
                     int write_dst) {
    extern __shared__ float sm[];
    float* At  = sm + SM_AT;    // [64][PA]  At[d][m]
    float* Bt  = sm + SM_BT;    // [64][PA]  Bt[d][n]
    float* Dt  = sm + SM_DT;    // [128][PD] d2 tile
    float* x2r = sm + SM_X2R;
    float* x2c = sm + SM_X2C;

    const int tid   = threadIdx.x;
    const int batch = blockIdx.x >> 6;          // 64 row-tiles per batch
    const int rtile = blockIdx.x & 63;
    const float* xb = x + (size_t)batch * MP * DD;
    const int row0  = rtile * TM;

    // ---- Prologue: A tile transposed to d-major ----
    #pragma unroll
    for (int it = 0; it < 8; ++it) {
        int idx = it * NTHREADS + tid;          // 0..2047
        int m   = idx & 127;
        int d4  = idx >> 7;                     // 0..15
        float4 v = *reinterpret_cast<const float4*>(xb + (size_t)(row0 + m) * DD + d4 * 4);
        At[(d4 * 4 + 0) * PA + m] = v.x;
        At[(d4 * 4 + 1) * PA + m] = v.y;
        At[(d4 * 4 + 2) * PA + m] = v.z;
        At[(d4 * 4 + 3) * PA + m] = v.w;
    }
    // ---- B tile 0: prefetch to regs, store ----
    float4 pf[8];
    #pragma unroll
    for (int it = 0; it < 8; ++it) {
        int idx = it * NTHREADS + tid;
        int n   = idx & 127;
        int d4  = idx >> 7;
        pf[it] = *reinterpret_cast<const float4*>(xb + (size_t)n * DD + d4 * 4);
    }
    #pragma unroll
    for (int it = 0; it < 8; ++it) {
        int idx = it * NTHREADS + tid;
        int n   = idx & 127;
        int d4  = idx >> 7;
        Bt[(d4 * 4 + 0) * PA + n] = pf[it].x;
        Bt[(d4 * 4 + 1) * PA + n] = pf[it].y;
        Bt[(d4 * 4 + 2) * PA + n] = pf[it].z;
        Bt[(d4 * 4 + 3) * PA + n] = pf[it].w;
    }
    __syncthreads();

    const int ty = tid >> 4;          // 0..15
    const int tx = tid & 15;          // 0..15
    const int r0 = ty * 8;            // 8 contiguous rows
    const int ca = tx * 4;            // cols ca..ca+3
    const int cb = 64 + tx * 4;       // cols cb..cb+3  (split halves: conflict-free)

    // scan assignment: 2 threads per row, each owns 64 columns of every tile
    const int srow = tid & 127;
    const int sh   = tid >> 7;        // 0 or 1
    const float* drow = &Dt[srow * PD + sh * 64];

    float best[KNN];
    int   bidx[KNN];
    #pragma unroll
    for (int i = 0; i < KNN; ++i) { best[i] = __int_as_float(0x7f800000); bidx[i] = 0; }

    for (int ct = 0; ct < MP / TN; ++ct) {
        // ================= P1: scan(ct-1) | x2 norms | prefetch | GEMM(ct) ====
        if (ct > 0) {
            const int cbase = (ct - 1) * TN + sh * 64;
            float b15 = best[KNN - 1];
            #pragma unroll 4
            for (int c = 0; c < 64; ++c) {
                float v = drow[c];
                if (v < b15) {
                    best[KNN - 1] = v;
                    bidx[KNN - 1] = cbase + c;
                    #pragma unroll
                    for (int j = KNN - 1; j > 0; --j) {
                        if (best[j] < best[j - 1]) {
                            float tv = best[j]; best[j] = best[j - 1]; best[j - 1] = tv;
                            int   ti = bidx[j]; bidx[j] = bidx[j - 1]; bidx[j - 1] = ti;
                        }
                    }
                    b15 = best[KNN - 1];
                }
            }
        }
        if (tid < 128) {
            if (ct == 0) {          // row norms once
                float s = 0.f;
                #pragma unroll
                for (int d = 0; d < DD; ++d) { float a = At[d * PA + tid]; s = fmaf(a, a, s); }
                x2r[tid] = s;
            }
            float s = 0.f;          // candidate norms for this tile
            #pragma unroll
            for (int d = 0; d < DD; ++d) { float b = Bt[d * PA + tid]; s = fmaf(b, b, s); }
            x2c[tid] = s;
        }
        // prefetch next B tile (hidden under GEMM)
        if (ct + 1 < MP / TN) {
            const int col0n = (ct + 1) * TN;
            #pragma unroll
            for (int it = 0; it < 8; ++it) {
                int idx = it * NTHREADS + tid;
                int n   = idx & 127;
                int d4  = idx >> 7;
                pf[it] = *reinterpret_cast<const float4*>(xb + (size_t)(col0n + n) * DD + d4 * 4);
            }
        }

        // ---- 128x128x64 GEMM, 8x8 micro-tile, packed f32x2 (rows paired) ----
        ull acc[4][8];
        #pragma unroll
        for (int ip = 0; ip < 4; ++ip)
            #pragma unroll
            for (int j = 0; j < 8; ++j) acc[ip][j] = 0ULL;

        #pragma unroll 8
        for (int k = 0; k < DD; ++k) {
            ulonglong2 a01 = *reinterpret_cast<const ulonglong2*>(&At[k * PA + r0]);
            ulonglong2 a23 = *reinterpret_cast<const ulonglong2*>(&At[k * PA + r0 + 4]);
            float4 bv0 = *reinterpret_cast<const float4*>(&Bt[k * PA + ca]);
            float4 bv1 = *reinterpret_cast<const float4*>(&Bt[k * PA + cb]);
            ull ap[4] = {a01.x, a01.y, a23.x, a23.y};
            float bs[8] = {bv0.x, bv0.y, bv0.z, bv0.w, bv1.x, bv1.y, bv1.z, bv1.w};
            #pragma unroll
            for (int j = 0; j < 8; ++j) {
                ull b2 = splat2(bs[j]);
                #pragma unroll
                for (int ip = 0; ip < 4; ++ip)
                    acc[ip][j] = ffma2(ap[ip], b2, acc[ip][j]);
            }
        }
        __syncthreads();

        // ================= P2: epilogue -> Dt | store prefetched Bt ==========
        {
            float xc[8];
            #pragma unroll
            for (int j = 0; j < 4; ++j) { xc[j] = x2c[ca + j]; xc[4 + j] = x2c[cb + j]; }
            #pragma unroll
            for (int ip = 0; ip < 4; ++ip) {
                int ra = r0 + ip * 2;
                float xra = x2r[ra], xrb = x2r[ra + 1];
                #pragma unroll
                for (int j = 0; j < 8; ++j) {
                    int col = (j < 4) ? (ca + j) : (cb + j - 4);
                    // t - 2*dot via fma: rounds identically to the reference
                    Dt[ra * PD + col]       = fmaf(-2.f, lane_lo(acc[ip][j]), xra + xc[j]);
                    Dt[(ra + 1) * PD + col] = fmaf(-2.f, lane_hi(acc[ip][j]), xrb + xc[j]);
                }
            }
        }
        if (ct + 1 < MP / TN) {
            #pragma unroll
            for (int it = 0; it < 8; ++it) {
                int idx = it * NTHREADS + tid;
                int n   = idx & 127;
                int d4  = idx >> 7;
                Bt[(d4 * 4 + 0) * PA + n] = pf[it].x;
                Bt[(d4 * 4 + 1) * PA + n] = pf[it].y;
                Bt[(d4 * 4 + 2) * PA + n] = pf[it].z;
                Bt[(d4 * 4 + 3) * PA + n] = pf[it].w;
            }
        }
        __syncthreads();
    }

    // ---- final scan (last tile) ----
    {
        const int cbase = (MP / TN - 1) * TN + sh * 64;
        float b15 = best[KNN - 1];
        #pragma unroll 4
        for (int c = 0; c < 64; ++c) {
            float v = drow[c];
            if (v < b15) {
                best[KNN - 1] = v;
                bidx[KNN - 1] = cbase + c;
                #pragma unroll
                for (int j = KNN - 1; j > 0; --j) {
                    if (best[j] < best[j - 1]) {
                        float tv = best[j]; best[j] = best[j - 1]; best[j - 1] = tv;
                        int   ti = bidx[j]; bidx[j] = bidx[j - 1]; bidx[j - 1] = ti;
                    }
                }
                b15 = best[KNN - 1];
            }
        }
    }
    __syncthreads();   // everyone done with At/Bt -> reuse as merge scratch

    // ---- merge the two half-lists per row (stable: ties -> lower index) ----
    float* vals = At;               // reuse: 128 rows x 32 entries
    int*   idxs = (int*)Bt;
    #pragma unroll
    for (int j = 0; j < KNN; ++j) {
        vals[srow * 32 + sh * KNN + j] = best[j];
        idxs[srow * 32 + sh * KNN + j] = bidx[j];
    }
    __syncthreads();

    if (tid < 128) {
        const int row = tid;
        const float* v0 = &vals[row * 32];
        const float* v1 = &vals[row * 32 + KNN];
        const int*   i0 = &idxs[row * 32];
        const int*   i1 = &idxs[row * 32 + KNN];
        int p0 = 0, p1 = 0;
        const int gid  = batch * MP + row0 + row;
        const int off  = batch * MP;
        const int base = gid * KNN;
        #pragma unroll
        for (int t = 0; t < KNN; ++t) {
            float a = (p0 < KNN) ? v0[p0] : __int_as_float(0x7f800000);
            float b = (p1 < KNN) ? v1[p1] : __int_as_float(0x7f800000);
            int   ia = (p0 < KNN) ? i0[p0] : 0x7fffffff;
            int   ib = (p1 < KNN) ? i1[p1] : 0x7fffffff;
            bool take0 = (a < b) || (a == b && ia < ib);
            int sel = take0 ? ia : ib;
            if (take0) ++p0; else ++p1;
            out[base + t] = (float)(sel + off);
        }
        if (write_dst) {
            float fgid = (float)gid;
            #pragma unroll
            for (int t = 0; t < KNN; ++t) out[NEDGES + base + t] = fgid;
        }
    }
}

extern "C" void kernel_launch(void* const* d_in, const int* in_sizes, int n_in,
                              void* d_out, int out_size) {
    // Bind x = largest input (robust to ordering and element/byte units).
    const float* x = (const float*)d_in[0];
    long long best_sz = -1;
    for (int i = 0; i < n_in; ++i) {
        if ((long long)in_sizes[i] > best_sz) {
            best_sz = in_sizes[i];
            x = (const float*)d_in[i];
        }
    }
    const int write_dst = (out_size >= 2 * NEDGES);

    cudaFuncSetAttribute(knn_topk_kernel,
                         cudaFuncAttributeMaxDynamicSharedMemorySize, SMEM_BYTES);
    knn_topk_kernel<<<NB * (MP / TM), NTHREADS, SMEM_BYTES>>>(x, (float*)d_out, write_dst);
}